// round 14
// baseline (speedup 1.0000x reference)
#include <cuda_runtime.h>
#include <math.h>
#include <stdint.h>

// ---------------- problem constants ----------------
#define BATCH 128
#define TLEN  300
#define LW    28
#define OUTN  28
#define SPN   7
#define EN    20
#define HN    256
#define WN    273          // T - L + 1
#define WOUT  245          // W - OUT
#define FIN   49           // L + 1 + E
#define BD    10           // distinct batch rows (b % 10)
#define MROWS (WN*BD)      // 2730

// output region boundaries (float32 elements, tuple order)
#define P0 878080          // prediction_values (245,128,28)
#define P1 1756160         // actual_values    (245,128,28)
#define P2 1759744         // holdout_prediction (128,28)
#define P3 2738176         // rnn_out (273,128,28)
#define P4 2741760         // hav (128,28)
#define P5 2745344         // hav_norm (128,28)

// ---------------- device scratch (no cudaMalloc allowed) ----------------
__device__ float g_Sfull[BATCH*307];
__device__ float g_levels[BATCH*TLEN];
__device__ float g_win[MROWS*FIN];
__device__ float g_Z[MROWS*1024];
__device__ float g_hA[MROWS*HN];
__device__ float g_hB[MROWS*HN];
__device__ float g_rnn[MROWS*OUTN];

// ---------------- helpers ----------------
__device__ __forceinline__ uint32_t s2u(const void* p){
    uint32_t a;
    asm("{ .reg .u64 t; cvta.to.shared.u64 t, %1; cvt.u32.u64 %0, t; }"
        : "=r"(a) : "l"(p));
    return a;
}
__device__ __forceinline__ float fast_sigmoid(float z){
    return __fdividef(1.f, 1.f + __expf(-z));
}
__device__ __forceinline__ float fast_tanh(float x){
    float a = fminf(fmaxf(x, -15.f), 15.f);
    float e = __expf(2.f*a);
    return __fdividef(e - 1.f, e + 1.f);
}

// ---------------- ES (Holt-Winters) smoothing ----------------
__global__ void es_kernel(const float* __restrict__ x,
                          const float* __restrict__ alpha_raw,
                          const float* __restrict__ gamma_raw,
                          const float* __restrict__ init_seas)
{
    __shared__ float ring[BATCH*SPN];
    int b = threadIdx.x;
    if (b >= BATCH) return;
    float a = fast_sigmoid(alpha_raw[b]);
    float g = fast_sigmoid(gamma_raw[b]);
    float s0 = 0.f;
    for (int k = 0; k < SPN; k++) {
        float s = __expf(init_seas[b*SPN + k]);
        g_Sfull[b*307 + k] = s;
        ring[b*SPN + k] = s;
        if (k == 0) s0 = s;
    }
    g_Sfull[b*307 + 7] = s0;
    float level = __fdividef(x[b*TLEN], s0);
    g_levels[b*TLEN] = level;
    for (int t = 1; t < TLEN; t++) {
        float xt = x[b*TLEN + t];
        int slot = t % SPN;
        float s = ring[b*SPN + slot];
        float lvl  = a*__fdividef(xt, s)   + (1.f - a)*level;
        float snew = g*__fdividef(xt, lvl) + (1.f - g)*s;
        ring[b*SPN + slot] = snew;
        g_Sfull[b*307 + t + 7] = snew;
        level = lvl;
        g_levels[b*TLEN + t] = lvl;
    }
}

// ---------------- build window_input (10 distinct batch rows) ----------
__global__ void build_win(const float* __restrict__ x,
                          const float* __restrict__ cats,
                          const float* __restrict__ myp)
{
    int idx = blockIdx.x*blockDim.x + threadIdx.x;
    if (idx >= MROWS*FIN) return;
    int f  = idx % FIN;
    int r  = idx / FIN;
    int bb = r % BD;
    int w  = r / BD;
    float v;
    if (f < LW) {
        int tt = w + f;
        v = __fdividef(__fdividef(x[bb*TLEN + tt], g_Sfull[bb*307 + tt]),
                       g_levels[bb*TLEN + 27 + w]);
    } else if (f < LW + EN) {
        v = cats[bb*EN + (f - LW)];
    } else {
        v = myp[0];
    }
    g_win[idx] = v;
}

// ---------------- generic SGEMM-NT (64x64; K=49, linear, score) -----------
// RES: adds R (same shape as A) to A on load.
template<int ACT, int RES>
__global__ void sgemm_nt(const float* __restrict__ A,
                         const float* __restrict__ R,
                         const float* __restrict__ Bm,
                         const float* __restrict__ bias,
                         float* __restrict__ C,
                         int M, int N, int K)
{
    __shared__ float As[16][64];
    __shared__ float Bs[16][64];
    const int tid = threadIdx.x;
    const int mBase = blockIdx.y * 64;
    const int nBase = blockIdx.x * 64;
    const int lr = tid >> 2;
    const int lk = (tid & 3) << 2;
    const int tx = tid & 15, ty = tid >> 4;
    float acc[4][4] = {};

    for (int k0 = 0; k0 < K; k0 += 16) {
        {
            const int m = mBase + lr;
            const int n = nBase + lr;
            #pragma unroll
            for (int i = 0; i < 4; i++) {
                int k = k0 + lk + i;
                float av = 0.f;
                if (m < M && k < K) {
                    av = A[m*K + k];
                    if (RES) av += R[m*K + k];
                }
                As[lk+i][lr] = av;
                Bs[lk+i][lr] = (n < N && k < K) ? Bm[n*K + k] : 0.f;
            }
        }
        __syncthreads();
        #pragma unroll
        for (int kk = 0; kk < 16; kk++) {
            const float4 a4 = *(const float4*)&As[kk][ty << 2];
            const float4 b4 = *(const float4*)&Bs[kk][tx << 2];
            float av[4] = {a4.x, a4.y, a4.z, a4.w};
            float bv[4] = {b4.x, b4.y, b4.z, b4.w};
            #pragma unroll
            for (int i = 0; i < 4; i++)
                #pragma unroll
                for (int j = 0; j < 4; j++)
                    acc[i][j] += av[i] * bv[j];
        }
        __syncthreads();
    }

    #pragma unroll
    for (int i = 0; i < 4; i++) {
        int m = mBase + (ty << 2) + i;
        if (m >= M) continue;
        #pragma unroll
        for (int j = 0; j < 4; j++) {
            int n = nBase + (tx << 2) + j;
            if (n >= N) continue;
            float v = acc[i][j] + bias[n];
            if (ACT == 1) v = tanhf(v);
            C[m*N + n] = v;
        }
    }
}

// ------- packed-f32x2 SGEMM-NT 128x128, BK=8, double-buffered, 2 CTA/SM -----
// Accumulators packed over n-pairs (u64 = two fp32 lanes). A is stored
// DUPLICATED in SMEM (As2[kk][i] = {a,a}) so the (a,a) operand comes straight
// from LDS.128 (ty-broadcast, conflict-free); B pairs are natural contiguous
// u64 from Bs. Inner loop: 32 fma.rn.f32x2 + 6 LDS.128 per kk (vs 64 FFMA + 4
// LDS scalar) -> ~1.8x issue reduction, 2x FMA-pipe throughput. Bit-identical
// rounding (f32x2 = two independent fp32 FMAs).
template<int ACT>
__global__ void __launch_bounds__(256,2)
sgemm128(const float* __restrict__ A,
         const float* __restrict__ Bm,
         const float* __restrict__ bias,
         float* __restrict__ C,
         int M, int N, int K)
{
    __shared__ __align__(16) float As2[2][8][128][2];   // i-duplicated pairs
    __shared__ __align__(16) float Bs[2][8][132];
    const int tid = threadIdx.x;
    const int mBase = blockIdx.y * 128;
    const int nBase = blockIdx.x * 128;
    const int tx = tid & 15, ty = tid >> 4;
    const int lrow = tid >> 1;
    const int lhalf = (tid & 1) * 4;
    const int mRow = mBase + lrow;
    const int nRow = nBase + lrow;

    unsigned long long acc[8][4];
    #pragma unroll
    for (int i = 0; i < 8; i++)
        #pragma unroll
        for (int j = 0; j < 4; j++) acc[i][j] = 0ull;

    float4 va = make_float4(0.f,0.f,0.f,0.f);
    float4 vb = make_float4(0.f,0.f,0.f,0.f);
    if (mRow < M) va = *(const float4*)&A[mRow*K + lhalf];
    if (nRow < N) vb = *(const float4*)&Bm[nRow*K + lhalf];

    int buf = 0;
    for (int k0 = 0; k0 < K; k0 += 8) {
        {
            float av[4] = {va.x, va.y, va.z, va.w};
            float bv[4] = {vb.x, vb.y, vb.z, vb.w};
            #pragma unroll
            for (int c = 0; c < 4; c++) {
                As2[buf][lhalf+c][lrow][0] = av[c];
                As2[buf][lhalf+c][lrow][1] = av[c];
                Bs[buf][lhalf+c][lrow] = bv[c];
            }
        }
        __syncthreads();

        if (k0 + 8 < K) {   // prefetch next slice (overlaps compute below)
            va = make_float4(0.f,0.f,0.f,0.f);
            vb = make_float4(0.f,0.f,0.f,0.f);
            if (mRow < M) va = *(const float4*)&A[mRow*K + k0 + 8 + lhalf];
            if (nRow < N) vb = *(const float4*)&Bm[nRow*K + k0 + 8 + lhalf];
        }

        #pragma unroll
        for (int kk = 0; kk < 8; kk++) {
            unsigned long long ad[8], bp[4];
            #pragma unroll
            for (int q = 0; q < 4; q++) {
                ulonglong2 t =
                    *(const ulonglong2*)&As2[buf][kk][ty*8 + 2*q][0];
                ad[2*q] = t.x; ad[2*q+1] = t.y;
            }
            {
                ulonglong2 t0 = *(const ulonglong2*)&Bs[buf][kk][tx*8];
                ulonglong2 t1 = *(const ulonglong2*)&Bs[buf][kk][tx*8+4];
                bp[0] = t0.x; bp[1] = t0.y; bp[2] = t1.x; bp[3] = t1.y;
            }
            #pragma unroll
            for (int i = 0; i < 8; i++)
                #pragma unroll
                for (int j = 0; j < 4; j++)
                    asm("fma.rn.f32x2 %0, %1, %2, %0;"
                        : "+l"(acc[i][j]) : "l"(ad[i]), "l"(bp[j]));
        }
        buf ^= 1;
    }

    #pragma unroll
    for (int i = 0; i < 8; i++) {
        int m = mBase + ty*8 + i;
        if (m >= M) continue;
        #pragma unroll
        for (int j = 0; j < 4; j++) {
            int n0 = nBase + tx*8 + 2*j;
            float lo = __uint_as_float((unsigned)acc[i][j]);
            float hi = __uint_as_float((unsigned)(acc[i][j] >> 32));
            if (n0 < N) {
                float v = lo + bias[n0];
                if (ACT == 1) v = tanhf(v);
                C[m*N + n0] = v;
            }
            if (n0 + 1 < N) {
                float v = hi + bias[n0+1];
                if (ACT == 1) v = tanhf(v);
                C[m*N + n0 + 1] = v;
            }
        }
    }
}

// ---------------- cluster-per-chain persistent LSTM recurrence --------------
// Round-10 proven version + DISTRIBUTED gate activations: each gate lane
// applies its own sigmoid/tanh in parallel BEFORE the gather, so the leader's
// serial tail is just fg*c+ig*gg and one tanh (was 4 sigmoids + 2 tanh).
template<int CPC, int D>
__global__ void __launch_bounds__(256,1) __cluster_dims__(8,1,1)
lstm_chain(const float* __restrict__ Z,
           const float* __restrict__ Whh,
           float* __restrict__ h)
{
    __shared__ __align__(16) float stage[2][CPC][256];  // parity double buffer

    const int tid = threadIdx.x;
    uint32_t rank;
    asm("mov.u32 %0, %%cluster_ctarank;" : "=r"(rank));
    const int U0 = (int)rank * 32;
    const int kp = tid & 1;
    const int g  = (tid >> 1) & 3;
    const int ul = tid >> 3;
    const int chBase = (blockIdx.x >> 3) * CPC;

    ulonglong2 w[32];
    {
        const ulonglong2* w16 =
            (const ulonglong2*)(Whh + (g*HN + U0 + ul)*HN + kp*128);
        #pragma unroll
        for (int i = 0; i < 32; i++) w[i] = w16[i];
    }

    for (int i = tid; i < 2*CPC*256; i += 256) ((float*)stage)[i] = 0.f;
    __syncthreads();
    asm volatile("barrier.cluster.arrive.aligned;" ::: "memory");
    asm volatile("barrier.cluster.wait.aligned;"   ::: "memory");

    const uint32_t stageAddr = s2u(&stage[0][0][0]);
    uint32_t rstage[8];
    #pragma unroll
    for (int rk = 0; rk < 8; rk++)
        asm("mapa.shared::cluster.u32 %0, %1, %2;"
            : "=r"(rstage[rk]) : "r"(stageAddr), "r"(rk));

    const int lane = tid & 31;
    const int gbase = lane & ~7;
    const bool leader = ((lane & 7) == 0);
    float cst[CPC];
    #pragma unroll
    for (int j = 0; j < CPC; j++) cst[j] = 0.f;

    const int nIter = (WN + D - 1) / D;

    float zv[CPC];
    #pragma unroll
    for (int j = 0; j < CPC; j++) {
        const int ch = chBase + j;
        const int t = (ch % D);
        zv[j] = (kp == 0 && t < WN)
              ? Z[(t*BD + ch/D)*1024 + g*HN + U0 + ul] : 0.f;
    }

    for (int it = 0; it < nIter; it++) {
        const int rp = (it + 1) & 1;
        const int wp = it & 1;

        #pragma unroll
        for (int j = 0; j < CPC; j++) {
            const int ch  = chBase + j;
            const int row = ch / D;
            const int t   = it*D + (ch % D);
            const ulonglong2* hp = (const ulonglong2*)&stage[rp][j][kp*128];
            unsigned long long p0a=0ull, p0b=0ull, p1a=0ull, p1b=0ull;
            #pragma unroll
            for (int i = 0; i < 32; i += 2) {
                ulonglong2 h0 = hp[i];
                ulonglong2 h1 = hp[i+1];
                asm("fma.rn.f32x2 %0, %1, %2, %0;" : "+l"(p0a) : "l"(w[i].x),   "l"(h0.x));
                asm("fma.rn.f32x2 %0, %1, %2, %0;" : "+l"(p1a) : "l"(w[i].y),   "l"(h0.y));
                asm("fma.rn.f32x2 %0, %1, %2, %0;" : "+l"(p0b) : "l"(w[i+1].x), "l"(h1.x));
                asm("fma.rn.f32x2 %0, %1, %2, %0;" : "+l"(p1b) : "l"(w[i+1].y), "l"(h1.y));
            }
            float v = __uint_as_float((unsigned)p0a) + __uint_as_float((unsigned)(p0a>>32))
                    + __uint_as_float((unsigned)p0b) + __uint_as_float((unsigned)(p0b>>32))
                    + __uint_as_float((unsigned)p1a) + __uint_as_float((unsigned)(p1a>>32))
                    + __uint_as_float((unsigned)p1b) + __uint_as_float((unsigned)(p1b>>32));
            v += __shfl_xor_sync(0xffffffffu, v, 1);     // kp reduce
            if (kp == 0) v += zv[j];

            // distributed activations: lane (kp=0, gate=g) transforms its own
            // pre-activation in parallel; tanh only for the g-gate (g==2).
            float sg = fast_sigmoid(v);
            float th = fast_tanh(v);
            float act = (g == 2) ? th : sg;

            float ig = __shfl_sync(0xffffffffu, act, gbase + 0);
            float fg = __shfl_sync(0xffffffffu, act, gbase + 2);
            float gg = __shfl_sync(0xffffffffu, act, gbase + 4);
            float og = __shfl_sync(0xffffffffu, act, gbase + 6);
            if (leader && t < WN) {
                float cn = fg*cst[j] + ig*gg;
                cst[j] = cn;
                float hn = og*fast_tanh(cn);
                h[(t*BD + row)*HN + U0 + ul] = hn;
                uint32_t off = ((wp*CPC + j)*256 + U0 + ul)*4;
                unsigned hu = __float_as_uint(hn);
                #pragma unroll
                for (int rk = 0; rk < 8; rk++)
                    asm volatile("st.shared::cluster.b32 [%0], %1;"
                                 :: "r"(rstage[rk] + off), "r"(hu) : "memory");
            }
        }

        asm volatile("barrier.cluster.arrive.aligned;" ::: "memory");

        #pragma unroll
        for (int j = 0; j < CPC; j++) {
            const int ch = chBase + j;
            const int t = (it+1)*D + (ch % D);
            zv[j] = (kp == 0 && t < WN && it+1 < nIter)
                  ? Z[(t*BD + ch/D)*1024 + g*HN + U0 + ul] : 0.f;
        }

        asm volatile("barrier.cluster.wait.aligned;" ::: "memory");
    }
}

// ---------------- assemble all six outputs ----------------------------------
__global__ void outputs_kernel(const float* __restrict__ x,
                               const float* __restrict__ val,
                               float* __restrict__ out, int out_size)
{
    for (int idx = blockIdx.x*blockDim.x + threadIdx.x; idx < out_size;
         idx += gridDim.x*blockDim.x)
    {
        float v = 0.f;
        if (idx < P0) {                              // prediction_values
            int w = idx / 3584; int rem = idx - w*3584;
            int b = rem / 28;   int j = rem - b*28;
            v = g_rnn[(w*BD + (b % BD))*OUTN + j];
        } else if (idx < P1) {                       // actual_values
            int i = idx - P0;
            int wo = i / 3584; int rem = i - wo*3584;
            int b = rem / 28;  int j = rem - b*28;
            int tt = 28 + wo + j;
            v = __fdividef(__fdividef(x[b*TLEN + tt], g_Sfull[b*307 + tt]),
                           g_levels[b*TLEN + 27 + wo]);
        } else if (idx < P2) {                       // holdout_prediction
            int i = idx - P1;
            int b = i / 28; int j = i - b*28;
            int k = 286 + j; if (k >= 307) k -= 7;
            float hh = g_rnn[(272*BD + (b % BD))*OUTN + j]
                       * g_Sfull[b*307 + k] * g_levels[b*TLEN + 299];
            v = hh > 0.f ? hh : 0.f;
        } else if (idx < P3) {                       // rnn_out
            int i = idx - P2;
            int w = i / 3584; int rem = i - w*3584;
            int b = rem / 28; int j = rem - b*28;
            v = g_rnn[(w*BD + (b % BD))*OUTN + j];
        } else if (idx < P4) {                       // hav
            v = val[idx - P3];
        } else if (idx < P5) {                       // hav_norm
            int i = idx - P4;
            int b = i / 28; int j = i - b*28;
            int k = 286 + j; if (k >= 307) k -= 7;
            v = __fdividef(__fdividef(val[b*28 + j], g_Sfull[b*307 + k]),
                           g_levels[b*TLEN + 299]);
        }
        out[idx] = v;
    }
}

// ---------------- host launcher ----------------------------------------------
extern "C" void kernel_launch(void* const* d_in, const int* in_sizes, int n_in,
                              void* d_out, int out_size)
{
    const float* x      = (const float*)d_in[0];
    const float* val    = (const float*)d_in[1];
    const float* alpha  = (const float*)d_in[2];
    const float* gamma  = (const float*)d_in[3];
    const float* iseas  = (const float*)d_in[4];
    const float* cats   = (const float*)d_in[5];
    const float* myp    = (const float*)d_in[6];
    const float* Wih1   = (const float*)d_in[7];
    const float* Whh1   = (const float*)d_in[8];
    const float* b1     = (const float*)d_in[9];
    const float* Wih2   = (const float*)d_in[10];
    const float* Whh2   = (const float*)d_in[11];
    const float* b2     = (const float*)d_in[12];
    const float* Wih3   = (const float*)d_in[13];
    const float* Whh3   = (const float*)d_in[14];
    const float* b3     = (const float*)d_in[15];
    const float* Wih4   = (const float*)d_in[16];
    const float* Whh4   = (const float*)d_in[17];
    const float* b4     = (const float*)d_in[18];
    const float* lW     = (const float*)d_in[19];
    const float* lb     = (const float*)d_in[20];
    const float* sW     = (const float*)d_in[21];
    const float* sb     = (const float*)d_in[22];

    float *pWin, *pZ, *pHA, *pHB, *pRnn;
    cudaGetSymbolAddress((void**)&pWin, g_win);
    cudaGetSymbolAddress((void**)&pZ,   g_Z);
    cudaGetSymbolAddress((void**)&pHA,  g_hA);
    cudaGetSymbolAddress((void**)&pHB,  g_hB);
    cudaGetSymbolAddress((void**)&pRnn, g_rnn);

    // 1) exponential smoothing + seasonals
    es_kernel<<<1, 128>>>(x, alpha, gamma, iseas);

    // 2) normalized window inputs (batch collapsed to 10 distinct rows)
    build_win<<<(MROWS*FIN + 255)/256, 256>>>(x, cats, myp);

    dim3 gBig128(8, (MROWS + 127)/128);   // N=1024, K=256 GEMMs

    // ---- layer 1 (d=1): K=49 input GEMM, then 10 clusters x 1 chain ----
    sgemm_nt<0,0><<<dim3(16, (MROWS+63)/64), 256>>>(
        pWin, nullptr, Wih1, b1, pZ, MROWS, 1024, FIN);
    lstm_chain<1,1><<<80, 256>>>(pZ, Whh1, pHA);

    // ---- layer 2 (d=2): -> hB (kept for residual) ----
    sgemm128<0><<<gBig128, 256>>>(pHA, Wih2, b2, pZ, MROWS, 1024, HN);
    lstm_chain<2,2><<<80, 256>>>(pZ, Whh2, pHB);

    // ---- layer 3 (d=2) ----
    sgemm128<0><<<gBig128, 256>>>(pHB, Wih3, b3, pZ, MROWS, 1024, HN);
    lstm_chain<2,2><<<80, 256>>>(pZ, Whh3, pHA);

    // ---- layer 4 (d=6): 15 clusters x 4 chains ----
    sgemm128<0><<<gBig128, 256>>>(pHA, Wih4, b4, pZ, MROWS, 1024, HN);
    lstm_chain<4,6><<<120, 256>>>(pZ, Whh4, pHA);

    // ---- linear + tanh with fused residual (hA + hB) -> g_Z (64x64 tiles) --
    sgemm_nt<1,1><<<dim3(4, (MROWS+63)/64), 256>>>(
        pHA, pHB, lW, lb, pZ, MROWS, HN, HN);

    // ---- score ----
    sgemm_nt<0,0><<<dim3(1, (MROWS+63)/64), 256>>>(
        pZ, nullptr, sW, sb, pRnn, MROWS, OUTN, HN);

    // ---- assemble outputs ----
    outputs_kernel<<<1024, 256>>>(x, val, (float*)d_out, out_size);
}

// round 15
// speedup vs baseline: 1.1964x; 1.1964x over previous
#include <cuda_runtime.h>
#include <math.h>
#include <stdint.h>

// ---------------- problem constants ----------------
#define BATCH 128
#define TLEN  300
#define LW    28
#define OUTN  28
#define SPN   7
#define EN    20
#define HN    256
#define WN    273          // T - L + 1
#define WOUT  245          // W - OUT
#define FIN   49           // L + 1 + E
#define BD    10           // distinct batch rows (b % 10)
#define MROWS (WN*BD)      // 2730

// output region boundaries (float32 elements, tuple order)
#define P0 878080          // prediction_values (245,128,28)
#define P1 1756160         // actual_values    (245,128,28)
#define P2 1759744         // holdout_prediction (128,28)
#define P3 2738176         // rnn_out (273,128,28)
#define P4 2741760         // hav (128,28)
#define P5 2745344         // hav_norm (128,28)

// ---------------- device scratch (no cudaMalloc allowed) ----------------
__device__ float g_Sfull[BATCH*307];
__device__ float g_levels[BATCH*TLEN];
__device__ float g_win[MROWS*FIN];
__device__ float g_Z[MROWS*1024];
__device__ float g_hA[MROWS*HN];
__device__ float g_hB[MROWS*HN];
__device__ float g_rnn[MROWS*OUTN];

// ---------------- helpers ----------------
__device__ __forceinline__ uint32_t s2u(const void* p){
    uint32_t a;
    asm("{ .reg .u64 t; cvta.to.shared.u64 t, %1; cvt.u32.u64 %0, t; }"
        : "=r"(a) : "l"(p));
    return a;
}
__device__ __forceinline__ float fast_sigmoid(float z){
    return __fdividef(1.f, 1.f + __expf(-z));
}
__device__ __forceinline__ float fast_tanh(float x){
    float a = fminf(fmaxf(x, -15.f), 15.f);
    float e = __expf(2.f*a);
    return __fdividef(e - 1.f, e + 1.f);
}

// ---------------- ES (Holt-Winters) smoothing ----------------
__global__ void es_kernel(const float* __restrict__ x,
                          const float* __restrict__ alpha_raw,
                          const float* __restrict__ gamma_raw,
                          const float* __restrict__ init_seas)
{
    __shared__ float ring[BATCH*SPN];
    int b = threadIdx.x;
    if (b >= BATCH) return;
    float a = fast_sigmoid(alpha_raw[b]);
    float g = fast_sigmoid(gamma_raw[b]);
    float s0 = 0.f;
    for (int k = 0; k < SPN; k++) {
        float s = __expf(init_seas[b*SPN + k]);
        g_Sfull[b*307 + k] = s;
        ring[b*SPN + k] = s;
        if (k == 0) s0 = s;
    }
    g_Sfull[b*307 + 7] = s0;
    float level = __fdividef(x[b*TLEN], s0);
    g_levels[b*TLEN] = level;
    for (int t = 1; t < TLEN; t++) {
        float xt = x[b*TLEN + t];
        int slot = t % SPN;
        float s = ring[b*SPN + slot];
        float lvl  = a*__fdividef(xt, s)   + (1.f - a)*level;
        float snew = g*__fdividef(xt, lvl) + (1.f - g)*s;
        ring[b*SPN + slot] = snew;
        g_Sfull[b*307 + t + 7] = snew;
        level = lvl;
        g_levels[b*TLEN + t] = lvl;
    }
}

// ---------------- build window_input (10 distinct batch rows) ----------
__global__ void build_win(const float* __restrict__ x,
                          const float* __restrict__ cats,
                          const float* __restrict__ myp)
{
    int idx = blockIdx.x*blockDim.x + threadIdx.x;
    if (idx >= MROWS*FIN) return;
    int f  = idx % FIN;
    int r  = idx / FIN;
    int bb = r % BD;
    int w  = r / BD;
    float v;
    if (f < LW) {
        int tt = w + f;
        v = __fdividef(__fdividef(x[bb*TLEN + tt], g_Sfull[bb*307 + tt]),
                       g_levels[bb*TLEN + 27 + w]);
    } else if (f < LW + EN) {
        v = cats[bb*EN + (f - LW)];
    } else {
        v = myp[0];
    }
    g_win[idx] = v;
}

// ---------------- generic SGEMM-NT (64x64; K=49, linear, score) -----------
// RES: adds R (same shape as A) to A on load.
template<int ACT, int RES>
__global__ void sgemm_nt(const float* __restrict__ A,
                         const float* __restrict__ R,
                         const float* __restrict__ Bm,
                         const float* __restrict__ bias,
                         float* __restrict__ C,
                         int M, int N, int K)
{
    __shared__ float As[16][64];
    __shared__ float Bs[16][64];
    const int tid = threadIdx.x;
    const int mBase = blockIdx.y * 64;
    const int nBase = blockIdx.x * 64;
    const int lr = tid >> 2;
    const int lk = (tid & 3) << 2;
    const int tx = tid & 15, ty = tid >> 4;
    float acc[4][4] = {};

    for (int k0 = 0; k0 < K; k0 += 16) {
        {
            const int m = mBase + lr;
            const int n = nBase + lr;
            #pragma unroll
            for (int i = 0; i < 4; i++) {
                int k = k0 + lk + i;
                float av = 0.f;
                if (m < M && k < K) {
                    av = A[m*K + k];
                    if (RES) av += R[m*K + k];
                }
                As[lk+i][lr] = av;
                Bs[lk+i][lr] = (n < N && k < K) ? Bm[n*K + k] : 0.f;
            }
        }
        __syncthreads();
        #pragma unroll
        for (int kk = 0; kk < 16; kk++) {
            const float4 a4 = *(const float4*)&As[kk][ty << 2];
            const float4 b4 = *(const float4*)&Bs[kk][tx << 2];
            float av[4] = {a4.x, a4.y, a4.z, a4.w};
            float bv[4] = {b4.x, b4.y, b4.z, b4.w};
            #pragma unroll
            for (int i = 0; i < 4; i++)
                #pragma unroll
                for (int j = 0; j < 4; j++)
                    acc[i][j] += av[i] * bv[j];
        }
        __syncthreads();
    }

    #pragma unroll
    for (int i = 0; i < 4; i++) {
        int m = mBase + (ty << 2) + i;
        if (m >= M) continue;
        #pragma unroll
        for (int j = 0; j < 4; j++) {
            int n = nBase + (tx << 2) + j;
            if (n >= N) continue;
            float v = acc[i][j] + bias[n];
            if (ACT == 1) v = tanhf(v);
            C[m*N + n] = v;
        }
    }
}

// ------- pipelined SGEMM-NT 128x128, BK=8, 8x8/thread, double-buffered -----
// (round-13 proven version)
template<int ACT>
__global__ void __launch_bounds__(256,2)
sgemm128(const float* __restrict__ A,
         const float* __restrict__ Bm,
         const float* __restrict__ bias,
         float* __restrict__ C,
         int M, int N, int K)
{
    __shared__ float As[2][8][132];
    __shared__ float Bs[2][8][132];
    const int tid = threadIdx.x;
    const int mBase = blockIdx.y * 128;
    const int nBase = blockIdx.x * 128;
    const int tx = tid & 15, ty = tid >> 4;
    const int lrow = tid >> 1;
    const int lhalf = (tid & 1) * 4;
    const int mRow = mBase + lrow;
    const int nRow = nBase + lrow;
    float acc[8][8] = {};

    float4 va = make_float4(0.f,0.f,0.f,0.f);
    float4 vb = make_float4(0.f,0.f,0.f,0.f);
    if (mRow < M) va = *(const float4*)&A[mRow*K + lhalf];
    if (nRow < N) vb = *(const float4*)&Bm[nRow*K + lhalf];

    int buf = 0;
    for (int k0 = 0; k0 < K; k0 += 8) {
        As[buf][lhalf+0][lrow] = va.x; As[buf][lhalf+1][lrow] = va.y;
        As[buf][lhalf+2][lrow] = va.z; As[buf][lhalf+3][lrow] = va.w;
        Bs[buf][lhalf+0][lrow] = vb.x; Bs[buf][lhalf+1][lrow] = vb.y;
        Bs[buf][lhalf+2][lrow] = vb.z; Bs[buf][lhalf+3][lrow] = vb.w;
        __syncthreads();

        if (k0 + 8 < K) {
            va = make_float4(0.f,0.f,0.f,0.f);
            vb = make_float4(0.f,0.f,0.f,0.f);
            if (mRow < M) va = *(const float4*)&A[mRow*K + k0 + 8 + lhalf];
            if (nRow < N) vb = *(const float4*)&Bm[nRow*K + k0 + 8 + lhalf];
        }

        #pragma unroll
        for (int kk = 0; kk < 8; kk++) {
            float a[8], b[8];
            *(float4*)&a[0] = *(const float4*)&As[buf][kk][ty*8];
            *(float4*)&a[4] = *(const float4*)&As[buf][kk][ty*8+4];
            *(float4*)&b[0] = *(const float4*)&Bs[buf][kk][tx*8];
            *(float4*)&b[4] = *(const float4*)&Bs[buf][kk][tx*8+4];
            #pragma unroll
            for (int i = 0; i < 8; i++)
                #pragma unroll
                for (int j = 0; j < 8; j++)
                    acc[i][j] = fmaf(a[i], b[j], acc[i][j]);
        }
        buf ^= 1;
    }
    #pragma unroll
    for (int i = 0; i < 8; i++) {
        int m = mBase + ty*8 + i;
        if (m >= M) continue;
        #pragma unroll
        for (int j = 0; j < 8; j++) {
            int n = nBase + tx*8 + j;
            if (n >= N) continue;
            float v = acc[i][j] + bias[n];
            if (ACT == 1) v = tanhf(v);
            C[m*N + n] = v;
        }
    }
}

// ---------------- cluster-per-chain persistent LSTM recurrence --------------
// st.async edition: NO cluster barrier in the loop. Each unit's h is sent to
// all 8 peer CTAs via st.async.shared::cluster.mbarrier::complete_tx::bytes
// (one send per thread: thread s of each gate-group targets rank s). Two
// mbarriers (even/odd step) track byte arrival (tx = 1024*CPC per step); the
// consumer try_waits on parity. Arming is done one phase AHEAD of any
// possible arrival: mbar[b]'s next phase is armed immediately after its
// current phase is consumed, strictly before this CTA sends the data that
// peers need to produce the next phase's bytes. Stage parity double buffer as
// before. Final cluster sync guards DSMEM lifetime at exit.
// Thread map: tid = kp(2) + 2*g(4) + 8*ul(32).
template<int CPC, int D>
__global__ void __launch_bounds__(256,1) __cluster_dims__(8,1,1)
lstm_chain(const float* __restrict__ Z,
           const float* __restrict__ Whh,
           float* __restrict__ h)
{
    __shared__ __align__(16) float stage[2][CPC][256];  // parity double buffer
    __shared__ __align__(8) unsigned long long mbar[2]; // even/odd step

    const int tid = threadIdx.x;
    uint32_t rank;
    asm("mov.u32 %0, %%cluster_ctarank;" : "=r"(rank));
    const int U0 = (int)rank * 32;
    const int kp = tid & 1;
    const int g  = (tid >> 1) & 3;
    const int ul = tid >> 3;
    const int chBase = (blockIdx.x >> 3) * CPC;
    const int nIter = (WN + D - 1) / D;
    const unsigned TXB = 1024u * CPC;   // bytes per step per mbar

    // Whh slice -> registers (row = g*HN + U0+ul, k half = kp*128..+128)
    ulonglong2 w[32];
    {
        const ulonglong2* w16 =
            (const ulonglong2*)(Whh + (g*HN + U0 + ul)*HN + kp*128);
        #pragma unroll
        for (int i = 0; i < 32; i++) w[i] = w16[i];
    }

    // init: zero stage, init mbarriers (count=1), pre-arm h_0 and h_1 phases
    for (int i = tid; i < 2*CPC*256; i += 256) ((float*)stage)[i] = 0.f;
    const uint32_t mbarAddr = s2u(&mbar[0]);
    if (tid < 2)
        asm volatile("mbarrier.init.shared.b64 [%0], %1;"
                     :: "r"(mbarAddr + tid*8u), "r"(1) : "memory");
    __syncthreads();
    if (tid == 0) {
        if (nIter > 1)   // arm mbar[0] for h_0
            asm volatile("mbarrier.arrive.expect_tx.shared.b64 _, [%0], %1;"
                         :: "r"(mbarAddr), "r"(TXB) : "memory");
        if (nIter > 2)   // arm mbar[1] for h_1
            asm volatile("mbarrier.arrive.expect_tx.shared.b64 _, [%0], %1;"
                         :: "r"(mbarAddr + 8u), "r"(TXB) : "memory");
    }
    __syncthreads();
    asm volatile("barrier.cluster.arrive.aligned;" ::: "memory");
    asm volatile("barrier.cluster.wait.aligned;"   ::: "memory");

    // peer apertures for stage + mbar
    const uint32_t stageAddr = s2u(&stage[0][0][0]);
    uint32_t rstage[8], rmbar[8];
    #pragma unroll
    for (int rk = 0; rk < 8; rk++) {
        asm("mapa.shared::cluster.u32 %0, %1, %2;"
            : "=r"(rstage[rk]) : "r"(stageAddr), "r"(rk));
        asm("mapa.shared::cluster.u32 %0, %1, %2;"
            : "=r"(rmbar[rk]) : "r"(mbarAddr), "r"(rk));
    }

    const int lane = tid & 31;
    const int gbase = lane & ~7;
    const int rkDst = tid & 7;               // this thread's destination rank
    const bool hwriter = (rkDst == 0);       // one global-h writer per unit
    float cst[CPC];
    #pragma unroll
    for (int j = 0; j < CPC; j++) cst[j] = 0.f;

    // prefetch Z for it=0
    float zv[CPC];
    #pragma unroll
    for (int j = 0; j < CPC; j++) {
        const int ch = chBase + j;
        const int t = (ch % D);
        zv[j] = (kp == 0 && t < WN)
              ? Z[(t*BD + ch/D)*1024 + g*HN + U0 + ul] : 0.f;
    }

    for (int it = 0; it < nIter; it++) {
        const int rp = (it + 1) & 1;   // read buffer (h from it-1)
        const int wp = it & 1;         // write buffer (h of it)

        // wait for h_{it-1} bytes (mbar[(it-1)&1], use index (it-1)>>1)
        if (it > 0) {
            uint32_t mb = mbarAddr + (uint32_t)(((it-1) & 1) << 3);
            uint32_t par = (uint32_t)(((it-1) >> 1) & 1);
            asm volatile(
                "{\n\t.reg .pred P;\n\t"
                "W%=:\n\t"
                "mbarrier.try_wait.parity.acquire.cluster.shared::cta.b64 P, [%0], %1, 0x989680;\n\t"
                "@P bra D%=;\n\t"
                "bra W%=;\n\t"
                "D%=:\n\t}"
                :: "r"(mb), "r"(par) : "memory");
            // re-arm this mbar for h_{it+1} BEFORE we send h_it (so no
            // h_{it+1} byte can ever precede the arm)
            if (tid == 0 && (it + 1) < nIter - 1)
                asm volatile("mbarrier.arrive.expect_tx.shared.b64 _, [%0], %1;"
                             :: "r"(mb), "r"(TXB) : "memory");
        }

        #pragma unroll
        for (int j = 0; j < CPC; j++) {
            const int ch  = chBase + j;
            const int row = ch / D;
            const int t   = it*D + (ch % D);
            const ulonglong2* hp = (const ulonglong2*)&stage[rp][j][kp*128];
            unsigned long long p0a=0ull, p0b=0ull, p1a=0ull, p1b=0ull;
            #pragma unroll
            for (int i = 0; i < 32; i += 2) {
                ulonglong2 h0 = hp[i];
                ulonglong2 h1 = hp[i+1];
                asm("fma.rn.f32x2 %0, %1, %2, %0;" : "+l"(p0a) : "l"(w[i].x),   "l"(h0.x));
                asm("fma.rn.f32x2 %0, %1, %2, %0;" : "+l"(p1a) : "l"(w[i].y),   "l"(h0.y));
                asm("fma.rn.f32x2 %0, %1, %2, %0;" : "+l"(p0b) : "l"(w[i+1].x), "l"(h1.x));
                asm("fma.rn.f32x2 %0, %1, %2, %0;" : "+l"(p1b) : "l"(w[i+1].y), "l"(h1.y));
            }
            float v = __uint_as_float((unsigned)p0a) + __uint_as_float((unsigned)(p0a>>32))
                    + __uint_as_float((unsigned)p0b) + __uint_as_float((unsigned)(p0b>>32))
                    + __uint_as_float((unsigned)p1a) + __uint_as_float((unsigned)(p1a>>32))
                    + __uint_as_float((unsigned)p1b) + __uint_as_float((unsigned)(p1b>>32));
            v += __shfl_xor_sync(0xffffffffu, v, 1);     // kp reduce
            if (kp == 0) v += zv[j];

            // distributed activations (gather sources are kp==0 lanes)
            float sg = fast_sigmoid(v);
            float th = fast_tanh(v);
            float act = (g == 2) ? th : sg;

            float ig = __shfl_sync(0xffffffffu, act, gbase + 0);
            float fg = __shfl_sync(0xffffffffu, act, gbase + 2);
            float gg = __shfl_sync(0xffffffffu, act, gbase + 4);
            float og = __shfl_sync(0xffffffffu, act, gbase + 6);

            // every thread in the gate-group keeps an identical cell state
            float cn = fg*cst[j] + ig*gg;
            cst[j] = cn;
            float hn = og*fast_tanh(cn);

            if (hwriter && t < WN)
                h[(t*BD + row)*HN + U0 + ul] = hn;

            if (it < nIter - 1) {
                // one st.async per thread: unit (U0+ul) -> rank rkDst
                uint32_t off = ((uint32_t)(wp*CPC + j)*256u + (uint32_t)(U0 + ul))*4u;
                unsigned hu = __float_as_uint(hn);
                asm volatile(
                    "st.async.shared::cluster.mbarrier::complete_tx::bytes.b32 [%0], %1, [%2];"
                    :: "r"(rstage[rkDst] + off), "r"(hu),
                       "r"(rmbar[rkDst] + (uint32_t)(wp << 3)) : "memory");
            }
        }

        // prefetch next Z (overlaps peer delivery; wait is at next loop top)
        #pragma unroll
        for (int j = 0; j < CPC; j++) {
            const int ch = chBase + j;
            const int t = (it+1)*D + (ch % D);
            zv[j] = (kp == 0 && t < WN && it+1 < nIter)
                  ? Z[(t*BD + ch/D)*1024 + g*HN + U0 + ul] : 0.f;
        }
    }

    // DSMEM lifetime: no CTA may exit while peers' st.async could be in flight
    asm volatile("barrier.cluster.arrive.aligned;" ::: "memory");
    asm volatile("barrier.cluster.wait.aligned;"   ::: "memory");
}

// ---------------- assemble all six outputs ----------------------------------
__global__ void outputs_kernel(const float* __restrict__ x,
                               const float* __restrict__ val,
                               float* __restrict__ out, int out_size)
{
    for (int idx = blockIdx.x*blockDim.x + threadIdx.x; idx < out_size;
         idx += gridDim.x*blockDim.x)
    {
        float v = 0.f;
        if (idx < P0) {                              // prediction_values
            int w = idx / 3584; int rem = idx - w*3584;
            int b = rem / 28;   int j = rem - b*28;
            v = g_rnn[(w*BD + (b % BD))*OUTN + j];
        } else if (idx < P1) {                       // actual_values
            int i = idx - P0;
            int wo = i / 3584; int rem = i - wo*3584;
            int b = rem / 28;  int j = rem - b*28;
            int tt = 28 + wo + j;
            v = __fdividef(__fdividef(x[b*TLEN + tt], g_Sfull[b*307 + tt]),
                           g_levels[b*TLEN + 27 + wo]);
        } else if (idx < P2) {                       // holdout_prediction
            int i = idx - P1;
            int b = i / 28; int j = i - b*28;
            int k = 286 + j; if (k >= 307) k -= 7;
            float hh = g_rnn[(272*BD + (b % BD))*OUTN + j]
                       * g_Sfull[b*307 + k] * g_levels[b*TLEN + 299];
            v = hh > 0.f ? hh : 0.f;
        } else if (idx < P3) {                       // rnn_out
            int i = idx - P2;
            int w = i / 3584; int rem = i - w*3584;
            int b = rem / 28; int j = rem - b*28;
            v = g_rnn[(w*BD + (b % BD))*OUTN + j];
        } else if (idx < P4) {                       // hav
            v = val[idx - P3];
        } else if (idx < P5) {                       // hav_norm
            int i = idx - P4;
            int b = i / 28; int j = i - b*28;
            int k = 286 + j; if (k >= 307) k -= 7;
            v = __fdividef(__fdividef(val[b*28 + j], g_Sfull[b*307 + k]),
                           g_levels[b*TLEN + 299]);
        }
        out[idx] = v;
    }
}

// ---------------- host launcher ----------------------------------------------
extern "C" void kernel_launch(void* const* d_in, const int* in_sizes, int n_in,
                              void* d_out, int out_size)
{
    const float* x      = (const float*)d_in[0];
    const float* val    = (const float*)d_in[1];
    const float* alpha  = (const float*)d_in[2];
    const float* gamma  = (const float*)d_in[3];
    const float* iseas  = (const float*)d_in[4];
    const float* cats   = (const float*)d_in[5];
    const float* myp    = (const float*)d_in[6];
    const float* Wih1   = (const float*)d_in[7];
    const float* Whh1   = (const float*)d_in[8];
    const float* b1     = (const float*)d_in[9];
    const float* Wih2   = (const float*)d_in[10];
    const float* Whh2   = (const float*)d_in[11];
    const float* b2     = (const float*)d_in[12];
    const float* Wih3   = (const float*)d_in[13];
    const float* Whh3   = (const float*)d_in[14];
    const float* b3     = (const float*)d_in[15];
    const float* Wih4   = (const float*)d_in[16];
    const float* Whh4   = (const float*)d_in[17];
    const float* b4     = (const float*)d_in[18];
    const float* lW     = (const float*)d_in[19];
    const float* lb     = (const float*)d_in[20];
    const float* sW     = (const float*)d_in[21];
    const float* sb     = (const float*)d_in[22];

    float *pWin, *pZ, *pHA, *pHB, *pRnn;
    cudaGetSymbolAddress((void**)&pWin, g_win);
    cudaGetSymbolAddress((void**)&pZ,   g_Z);
    cudaGetSymbolAddress((void**)&pHA,  g_hA);
    cudaGetSymbolAddress((void**)&pHB,  g_hB);
    cudaGetSymbolAddress((void**)&pRnn, g_rnn);

    // 1) exponential smoothing + seasonals
    es_kernel<<<1, 128>>>(x, alpha, gamma, iseas);

    // 2) normalized window inputs (batch collapsed to 10 distinct rows)
    build_win<<<(MROWS*FIN + 255)/256, 256>>>(x, cats, myp);

    dim3 gBig128(8, (MROWS + 127)/128);   // N=1024, K=256 GEMMs

    // ---- layer 1 (d=1): K=49 input GEMM, then 10 clusters x 1 chain ----
    sgemm_nt<0,0><<<dim3(16, (MROWS+63)/64), 256>>>(
        pWin, nullptr, Wih1, b1, pZ, MROWS, 1024, FIN);
    lstm_chain<1,1><<<80, 256>>>(pZ, Whh1, pHA);

    // ---- layer 2 (d=2): -> hB (kept for residual) ----
    sgemm128<0><<<gBig128, 256>>>(pHA, Wih2, b2, pZ, MROWS, 1024, HN);
    lstm_chain<2,2><<<80, 256>>>(pZ, Whh2, pHB);

    // ---- layer 3 (d=2) ----
    sgemm128<0><<<gBig128, 256>>>(pHB, Wih3, b3, pZ, MROWS, 1024, HN);
    lstm_chain<2,2><<<80, 256>>>(pZ, Whh3, pHA);

    // ---- layer 4 (d=6): 15 clusters x 4 chains ----
    sgemm128<0><<<gBig128, 256>>>(pHA, Wih4, b4, pZ, MROWS, 1024, HN);
    lstm_chain<4,6><<<120, 256>>>(pZ, Whh4, pHA);

    // ---- linear + tanh with fused residual (hA + hB) -> g_Z (64x64 tiles) --
    sgemm_nt<1,1><<<dim3(4, (MROWS+63)/64), 256>>>(
        pHA, pHB, lW, lb, pZ, MROWS, HN, HN);

    // ---- score ----
    sgemm_nt<0,0><<<dim3(1, (MROWS+63)/64), 256>>>(
        pZ, nullptr, sW, sb, pRnn, MROWS, OUTN, HN);

    // ---- assemble outputs ----
    outputs_kernel<<<1024, 256>>>(x, val, (float*)d_out, out_size);
}

// round 16
// speedup vs baseline: 1.2423x; 1.0384x over previous
#include <cuda_runtime.h>
#include <math.h>
#include <stdint.h>

// ---------------- problem constants ----------------
#define BATCH 128
#define TLEN  300
#define LW    28
#define OUTN  28
#define SPN   7
#define EN    20
#define HN    256
#define WN    273          // T - L + 1
#define WOUT  245          // W - OUT
#define FIN   49           // L + 1 + E
#define BD    10           // distinct batch rows (b % 10)
#define MROWS (WN*BD)      // 2730

// output region boundaries (float32 elements, tuple order)
#define P0 878080          // prediction_values (245,128,28)
#define P1 1756160         // actual_values    (245,128,28)
#define P2 1759744         // holdout_prediction (128,28)
#define P3 2738176         // rnn_out (273,128,28)
#define P4 2741760         // hav (128,28)
#define P5 2745344         // hav_norm (128,28)

// ---------------- device scratch (no cudaMalloc allowed) ----------------
__device__ float g_Sfull[BATCH*307];
__device__ float g_levels[BATCH*TLEN];
__device__ float g_win[MROWS*FIN];
__device__ float g_Z[MROWS*1024];
__device__ float g_hA[MROWS*HN];
__device__ float g_hB[MROWS*HN];
__device__ float g_rnn[MROWS*OUTN];

// ---------------- helpers ----------------
__device__ __forceinline__ uint32_t s2u(const void* p){
    uint32_t a;
    asm("{ .reg .u64 t; cvta.to.shared.u64 t, %1; cvt.u32.u64 %0, t; }"
        : "=r"(a) : "l"(p));
    return a;
}
__device__ __forceinline__ float fast_sigmoid(float z){
    return __fdividef(1.f, 1.f + __expf(-z));
}
__device__ __forceinline__ float fast_tanh(float x){
    // exact identity tanh(x) = 2*sigmoid(2x) - 1 (one exp chain)
    return 2.f*fast_sigmoid(2.f*x) - 1.f;
}

// ---------------- ES (Holt-Winters) smoothing ----------------
__global__ void es_kernel(const float* __restrict__ x,
                          const float* __restrict__ alpha_raw,
                          const float* __restrict__ gamma_raw,
                          const float* __restrict__ init_seas)
{
    __shared__ float ring[BATCH*SPN];
    int b = threadIdx.x;
    if (b >= BATCH) return;
    float a = fast_sigmoid(alpha_raw[b]);
    float g = fast_sigmoid(gamma_raw[b]);
    float s0 = 0.f;
    for (int k = 0; k < SPN; k++) {
        float s = __expf(init_seas[b*SPN + k]);
        g_Sfull[b*307 + k] = s;
        ring[b*SPN + k] = s;
        if (k == 0) s0 = s;
    }
    g_Sfull[b*307 + 7] = s0;
    float level = __fdividef(x[b*TLEN], s0);
    g_levels[b*TLEN] = level;
    for (int t = 1; t < TLEN; t++) {
        float xt = x[b*TLEN + t];
        int slot = t % SPN;
        float s = ring[b*SPN + slot];
        float lvl  = a*__fdividef(xt, s)   + (1.f - a)*level;
        float snew = g*__fdividef(xt, lvl) + (1.f - g)*s;
        ring[b*SPN + slot] = snew;
        g_Sfull[b*307 + t + 7] = snew;
        level = lvl;
        g_levels[b*TLEN + t] = lvl;
    }
}

// ---------------- build window_input (10 distinct batch rows) ----------
__global__ void build_win(const float* __restrict__ x,
                          const float* __restrict__ cats,
                          const float* __restrict__ myp)
{
    int idx = blockIdx.x*blockDim.x + threadIdx.x;
    if (idx >= MROWS*FIN) return;
    int f  = idx % FIN;
    int r  = idx / FIN;
    int bb = r % BD;
    int w  = r / BD;
    float v;
    if (f < LW) {
        int tt = w + f;
        v = __fdividef(__fdividef(x[bb*TLEN + tt], g_Sfull[bb*307 + tt]),
                       g_levels[bb*TLEN + 27 + w]);
    } else if (f < LW + EN) {
        v = cats[bb*EN + (f - LW)];
    } else {
        v = myp[0];
    }
    g_win[idx] = v;
}

// ---------------- generic SGEMM-NT (64x64; K=49, linear, score) -----------
// RES: adds R (same shape as A) to A on load.
template<int ACT, int RES>
__global__ void sgemm_nt(const float* __restrict__ A,
                         const float* __restrict__ R,
                         const float* __restrict__ Bm,
                         const float* __restrict__ bias,
                         float* __restrict__ C,
                         int M, int N, int K)
{
    __shared__ float As[16][64];
    __shared__ float Bs[16][64];
    const int tid = threadIdx.x;
    const int mBase = blockIdx.y * 64;
    const int nBase = blockIdx.x * 64;
    const int lr = tid >> 2;
    const int lk = (tid & 3) << 2;
    const int tx = tid & 15, ty = tid >> 4;
    float acc[4][4] = {};

    for (int k0 = 0; k0 < K; k0 += 16) {
        {
            const int m = mBase + lr;
            const int n = nBase + lr;
            #pragma unroll
            for (int i = 0; i < 4; i++) {
                int k = k0 + lk + i;
                float av = 0.f;
                if (m < M && k < K) {
                    av = A[m*K + k];
                    if (RES) av += R[m*K + k];
                }
                As[lk+i][lr] = av;
                Bs[lk+i][lr] = (n < N && k < K) ? Bm[n*K + k] : 0.f;
            }
        }
        __syncthreads();
        #pragma unroll
        for (int kk = 0; kk < 16; kk++) {
            const float4 a4 = *(const float4*)&As[kk][ty << 2];
            const float4 b4 = *(const float4*)&Bs[kk][tx << 2];
            float av[4] = {a4.x, a4.y, a4.z, a4.w};
            float bv[4] = {b4.x, b4.y, b4.z, b4.w};
            #pragma unroll
            for (int i = 0; i < 4; i++)
                #pragma unroll
                for (int j = 0; j < 4; j++)
                    acc[i][j] += av[i] * bv[j];
        }
        __syncthreads();
    }

    #pragma unroll
    for (int i = 0; i < 4; i++) {
        int m = mBase + (ty << 2) + i;
        if (m >= M) continue;
        #pragma unroll
        for (int j = 0; j < 4; j++) {
            int n = nBase + (tx << 2) + j;
            if (n >= N) continue;
            float v = acc[i][j] + bias[n];
            if (ACT == 1) v = tanhf(v);
            C[m*N + n] = v;
        }
    }
}

// ------- pipelined SGEMM-NT 128x128, BK=8, 8x8/thread, double-buffered -----
// (round-13 proven version)
template<int ACT>
__global__ void __launch_bounds__(256,2)
sgemm128(const float* __restrict__ A,
         const float* __restrict__ Bm,
         const float* __restrict__ bias,
         float* __restrict__ C,
         int M, int N, int K)
{
    __shared__ float As[2][8][132];
    __shared__ float Bs[2][8][132];
    const int tid = threadIdx.x;
    const int mBase = blockIdx.y * 128;
    const int nBase = blockIdx.x * 128;
    const int tx = tid & 15, ty = tid >> 4;
    const int lrow = tid >> 1;
    const int lhalf = (tid & 1) * 4;
    const int mRow = mBase + lrow;
    const int nRow = nBase + lrow;
    float acc[8][8] = {};

    float4 va = make_float4(0.f,0.f,0.f,0.f);
    float4 vb = make_float4(0.f,0.f,0.f,0.f);
    if (mRow < M) va = *(const float4*)&A[mRow*K + lhalf];
    if (nRow < N) vb = *(const float4*)&Bm[nRow*K + lhalf];

    int buf = 0;
    for (int k0 = 0; k0 < K; k0 += 8) {
        As[buf][lhalf+0][lrow] = va.x; As[buf][lhalf+1][lrow] = va.y;
        As[buf][lhalf+2][lrow] = va.z; As[buf][lhalf+3][lrow] = va.w;
        Bs[buf][lhalf+0][lrow] = vb.x; Bs[buf][lhalf+1][lrow] = vb.y;
        Bs[buf][lhalf+2][lrow] = vb.z; Bs[buf][lhalf+3][lrow] = vb.w;
        __syncthreads();

        if (k0 + 8 < K) {
            va = make_float4(0.f,0.f,0.f,0.f);
            vb = make_float4(0.f,0.f,0.f,0.f);
            if (mRow < M) va = *(const float4*)&A[mRow*K + k0 + 8 + lhalf];
            if (nRow < N) vb = *(const float4*)&Bm[nRow*K + k0 + 8 + lhalf];
        }

        #pragma unroll
        for (int kk = 0; kk < 8; kk++) {
            float a[8], b[8];
            *(float4*)&a[0] = *(const float4*)&As[buf][kk][ty*8];
            *(float4*)&a[4] = *(const float4*)&As[buf][kk][ty*8+4];
            *(float4*)&b[0] = *(const float4*)&Bs[buf][kk][tx*8];
            *(float4*)&b[4] = *(const float4*)&Bs[buf][kk][tx*8+4];
            #pragma unroll
            for (int i = 0; i < 8; i++)
                #pragma unroll
                for (int j = 0; j < 8; j++)
                    acc[i][j] = fmaf(a[i], b[j], acc[i][j]);
        }
        buf ^= 1;
    }
    #pragma unroll
    for (int i = 0; i < 8; i++) {
        int m = mBase + ty*8 + i;
        if (m >= M) continue;
        #pragma unroll
        for (int j = 0; j < 8; j++) {
            int n = nBase + tx*8 + j;
            if (n >= N) continue;
            float v = acc[i][j] + bias[n];
            if (ACT == 1) v = tanhf(v);
            C[m*N + n] = v;
        }
    }
}

// ---------------- cluster-per-chain persistent LSTM recurrence --------------
// st.async edition, b64-PAIRED sends: each unit-pair (ul, ul^1) is packed via
// shfl.xor(8) and sent as ONE st.async.b64 by the even-ul thread -> 128
// messages/CTA/step instead of 256, halving the serialized complete_tx
// updates at the receiver mbarrier. Two mbarriers (even/odd step) with
// ahead-of-time arming as in round 15. Single-exp activations via
// tanh(x)=2*sigmoid(2x)-1 (FSEL-selected per gate, no divergence).
// Thread map: tid = kp(2) + 2*g(4) + 8*ul(32).
template<int CPC, int D>
__global__ void __launch_bounds__(256,1) __cluster_dims__(8,1,1)
lstm_chain(const float* __restrict__ Z,
           const float* __restrict__ Whh,
           float* __restrict__ h)
{
    __shared__ __align__(16) float stage[2][CPC][256];  // parity double buffer
    __shared__ __align__(8) unsigned long long mbar[2]; // even/odd step

    const int tid = threadIdx.x;
    uint32_t rank;
    asm("mov.u32 %0, %%cluster_ctarank;" : "=r"(rank));
    const int U0 = (int)rank * 32;
    const int kp = tid & 1;
    const int g  = (tid >> 1) & 3;
    const int ul = tid >> 3;
    const int chBase = (blockIdx.x >> 3) * CPC;
    const int nIter = (WN + D - 1) / D;
    const unsigned TXB = 1024u * CPC;   // bytes per step per mbar

    // Whh slice -> registers (row = g*HN + U0+ul, k half = kp*128..+128)
    ulonglong2 w[32];
    {
        const ulonglong2* w16 =
            (const ulonglong2*)(Whh + (g*HN + U0 + ul)*HN + kp*128);
        #pragma unroll
        for (int i = 0; i < 32; i++) w[i] = w16[i];
    }

    // init: zero stage, init mbarriers (count=1), pre-arm h_0 and h_1 phases
    for (int i = tid; i < 2*CPC*256; i += 256) ((float*)stage)[i] = 0.f;
    const uint32_t mbarAddr = s2u(&mbar[0]);
    if (tid < 2)
        asm volatile("mbarrier.init.shared.b64 [%0], %1;"
                     :: "r"(mbarAddr + tid*8u), "r"(1) : "memory");
    __syncthreads();
    if (tid == 0) {
        if (nIter > 1)   // arm mbar[0] for h_0
            asm volatile("mbarrier.arrive.expect_tx.shared.b64 _, [%0], %1;"
                         :: "r"(mbarAddr), "r"(TXB) : "memory");
        if (nIter > 2)   // arm mbar[1] for h_1
            asm volatile("mbarrier.arrive.expect_tx.shared.b64 _, [%0], %1;"
                         :: "r"(mbarAddr + 8u), "r"(TXB) : "memory");
    }
    __syncthreads();
    asm volatile("barrier.cluster.arrive.aligned;" ::: "memory");
    asm volatile("barrier.cluster.wait.aligned;"   ::: "memory");

    // peer apertures for stage + mbar
    const uint32_t stageAddr = s2u(&stage[0][0][0]);
    uint32_t rstage[8], rmbar[8];
    #pragma unroll
    for (int rk = 0; rk < 8; rk++) {
        asm("mapa.shared::cluster.u32 %0, %1, %2;"
            : "=r"(rstage[rk]) : "r"(stageAddr), "r"(rk));
        asm("mapa.shared::cluster.u32 %0, %1, %2;"
            : "=r"(rmbar[rk]) : "r"(mbarAddr), "r"(rk));
    }

    const int lane = tid & 31;
    const int gbase = lane & ~7;
    const int rkDst = tid & 7;               // this thread's destination rank
    const bool hwriter = (rkDst == 0);       // one global-h writer per unit
    const bool sender  = ((ul & 1) == 0);    // even-ul threads send the pair
    float cst[CPC];
    #pragma unroll
    for (int j = 0; j < CPC; j++) cst[j] = 0.f;

    // per-gate activation constants: tanh(x)=2*sigmoid(2x)-1 for gate g==2
    const float aScl = (g == 2) ? 2.f : 1.f;
    const float aMul = (g == 2) ? 2.f : 1.f;
    const float aAdd = (g == 2) ? -1.f : 0.f;

    // prefetch Z for it=0
    float zv[CPC];
    #pragma unroll
    for (int j = 0; j < CPC; j++) {
        const int ch = chBase + j;
        const int t = (ch % D);
        zv[j] = (kp == 0 && t < WN)
              ? Z[(t*BD + ch/D)*1024 + g*HN + U0 + ul] : 0.f;
    }

    for (int it = 0; it < nIter; it++) {
        const int rp = (it + 1) & 1;   // read buffer (h from it-1)
        const int wp = it & 1;         // write buffer (h of it)

        // wait for h_{it-1} bytes (mbar[(it-1)&1], parity (it-1)>>1)
        if (it > 0) {
            uint32_t mb = mbarAddr + (uint32_t)(((it-1) & 1) << 3);
            uint32_t par = (uint32_t)(((it-1) >> 1) & 1);
            asm volatile(
                "{\n\t.reg .pred P;\n\t"
                "W%=:\n\t"
                "mbarrier.try_wait.parity.acquire.cluster.shared::cta.b64 P, [%0], %1, 0x989680;\n\t"
                "@P bra D%=;\n\t"
                "bra W%=;\n\t"
                "D%=:\n\t}"
                :: "r"(mb), "r"(par) : "memory");
            // re-arm this mbar for h_{it+1} BEFORE we send h_it
            if (tid == 0 && (it + 1) < nIter - 1)
                asm volatile("mbarrier.arrive.expect_tx.shared.b64 _, [%0], %1;"
                             :: "r"(mb), "r"(TXB) : "memory");
        }

        #pragma unroll
        for (int j = 0; j < CPC; j++) {
            const int ch  = chBase + j;
            const int row = ch / D;
            const int t   = it*D + (ch % D);
            const ulonglong2* hp = (const ulonglong2*)&stage[rp][j][kp*128];
            unsigned long long p0a=0ull, p0b=0ull, p1a=0ull, p1b=0ull;
            #pragma unroll
            for (int i = 0; i < 32; i += 2) {
                ulonglong2 h0 = hp[i];
                ulonglong2 h1 = hp[i+1];
                asm("fma.rn.f32x2 %0, %1, %2, %0;" : "+l"(p0a) : "l"(w[i].x),   "l"(h0.x));
                asm("fma.rn.f32x2 %0, %1, %2, %0;" : "+l"(p1a) : "l"(w[i].y),   "l"(h0.y));
                asm("fma.rn.f32x2 %0, %1, %2, %0;" : "+l"(p0b) : "l"(w[i+1].x), "l"(h1.x));
                asm("fma.rn.f32x2 %0, %1, %2, %0;" : "+l"(p1b) : "l"(w[i+1].y), "l"(h1.y));
            }
            float v = __uint_as_float((unsigned)p0a) + __uint_as_float((unsigned)(p0a>>32))
                    + __uint_as_float((unsigned)p0b) + __uint_as_float((unsigned)(p0b>>32))
                    + __uint_as_float((unsigned)p1a) + __uint_as_float((unsigned)(p1a>>32))
                    + __uint_as_float((unsigned)p1b) + __uint_as_float((unsigned)(p1b>>32));
            v += __shfl_xor_sync(0xffffffffu, v, 1);     // kp reduce
            if (kp == 0) v += zv[j];

            // single-exp activation, gate-selected (no divergence)
            float act = fast_sigmoid(aScl * v) * aMul + aAdd;

            float ig = __shfl_sync(0xffffffffu, act, gbase + 0);
            float fg = __shfl_sync(0xffffffffu, act, gbase + 2);
            float gg = __shfl_sync(0xffffffffu, act, gbase + 4);
            float og = __shfl_sync(0xffffffffu, act, gbase + 6);

            // every thread in the gate-group keeps an identical cell state
            float cn = fg*cst[j] + ig*gg;
            cst[j] = cn;
            float hn = og*fast_tanh(cn);

            if (hwriter && t < WN)
                h[(t*BD + row)*HN + U0 + ul] = hn;

            // pair units (ul, ul^1) and send ONE b64 per pair per rank
            float partner = __shfl_xor_sync(0xffffffffu, hn, 8);
            if (it < nIter - 1 && sender) {
                unsigned long long pk =
                    ((unsigned long long)__float_as_uint(partner) << 32)
                    | (unsigned long long)__float_as_uint(hn);
                uint32_t off = ((uint32_t)(wp*CPC + j)*256u
                                + (uint32_t)(U0 + ul))*4u;
                asm volatile(
                    "st.async.shared::cluster.mbarrier::complete_tx::bytes.b64 [%0], %1, [%2];"
                    :: "r"(rstage[rkDst] + off), "l"(pk),
                       "r"(rmbar[rkDst] + (uint32_t)(wp << 3)) : "memory");
            }
        }

        // prefetch next Z (overlaps peer delivery; wait is at next loop top)
        #pragma unroll
        for (int j = 0; j < CPC; j++) {
            const int ch = chBase + j;
            const int t = (it+1)*D + (ch % D);
            zv[j] = (kp == 0 && t < WN && it+1 < nIter)
                  ? Z[(t*BD + ch/D)*1024 + g*HN + U0 + ul] : 0.f;
        }
    }

    // DSMEM lifetime: no CTA may exit while peers' st.async could be in flight
    asm volatile("barrier.cluster.arrive.aligned;" ::: "memory");
    asm volatile("barrier.cluster.wait.aligned;"   ::: "memory");
}

// ---------------- assemble all six outputs ----------------------------------
__global__ void outputs_kernel(const float* __restrict__ x,
                               const float* __restrict__ val,
                               float* __restrict__ out, int out_size)
{
    for (int idx = blockIdx.x*blockDim.x + threadIdx.x; idx < out_size;
         idx += gridDim.x*blockDim.x)
    {
        float v = 0.f;
        if (idx < P0) {                              // prediction_values
            int w = idx / 3584; int rem = idx - w*3584;
            int b = rem / 28;   int j = rem - b*28;
            v = g_rnn[(w*BD + (b % BD))*OUTN + j];
        } else if (idx < P1) {                       // actual_values
            int i = idx - P0;
            int wo = i / 3584; int rem = i - wo*3584;
            int b = rem / 28;  int j = rem - b*28;
            int tt = 28 + wo + j;
            v = __fdividef(__fdividef(x[b*TLEN + tt], g_Sfull[b*307 + tt]),
                           g_levels[b*TLEN + 27 + wo]);
        } else if (idx < P2) {                       // holdout_prediction
            int i = idx - P1;
            int b = i / 28; int j = i - b*28;
            int k = 286 + j; if (k >= 307) k -= 7;
            float hh = g_rnn[(272*BD + (b % BD))*OUTN + j]
                       * g_Sfull[b*307 + k] * g_levels[b*TLEN + 299];
            v = hh > 0.f ? hh : 0.f;
        } else if (idx < P3) {                       // rnn_out
            int i = idx - P2;
            int w = i / 3584; int rem = i - w*3584;
            int b = rem / 28; int j = rem - b*28;
            v = g_rnn[(w*BD + (b % BD))*OUTN + j];
        } else if (idx < P4) {                       // hav
            v = val[idx - P3];
        } else if (idx < P5) {                       // hav_norm
            int i = idx - P4;
            int b = i / 28; int j = i - b*28;
            int k = 286 + j; if (k >= 307) k -= 7;
            v = __fdividef(__fdividef(val[b*28 + j], g_Sfull[b*307 + k]),
                           g_levels[b*TLEN + 299]);
        }
        out[idx] = v;
    }
}

// ---------------- host launcher ----------------------------------------------
extern "C" void kernel_launch(void* const* d_in, const int* in_sizes, int n_in,
                              void* d_out, int out_size)
{
    const float* x      = (const float*)d_in[0];
    const float* val    = (const float*)d_in[1];
    const float* alpha  = (const float*)d_in[2];
    const float* gamma  = (const float*)d_in[3];
    const float* iseas  = (const float*)d_in[4];
    const float* cats   = (const float*)d_in[5];
    const float* myp    = (const float*)d_in[6];
    const float* Wih1   = (const float*)d_in[7];
    const float* Whh1   = (const float*)d_in[8];
    const float* b1     = (const float*)d_in[9];
    const float* Wih2   = (const float*)d_in[10];
    const float* Whh2   = (const float*)d_in[11];
    const float* b2     = (const float*)d_in[12];
    const float* Wih3   = (const float*)d_in[13];
    const float* Whh3   = (const float*)d_in[14];
    const float* b3     = (const float*)d_in[15];
    const float* Wih4   = (const float*)d_in[16];
    const float* Whh4   = (const float*)d_in[17];
    const float* b4     = (const float*)d_in[18];
    const float* lW     = (const float*)d_in[19];
    const float* lb     = (const float*)d_in[20];
    const float* sW     = (const float*)d_in[21];
    const float* sb     = (const float*)d_in[22];

    float *pWin, *pZ, *pHA, *pHB, *pRnn;
    cudaGetSymbolAddress((void**)&pWin, g_win);
    cudaGetSymbolAddress((void**)&pZ,   g_Z);
    cudaGetSymbolAddress((void**)&pHA,  g_hA);
    cudaGetSymbolAddress((void**)&pHB,  g_hB);
    cudaGetSymbolAddress((void**)&pRnn, g_rnn);

    // 1) exponential smoothing + seasonals
    es_kernel<<<1, 128>>>(x, alpha, gamma, iseas);

    // 2) normalized window inputs (batch collapsed to 10 distinct rows)
    build_win<<<(MROWS*FIN + 255)/256, 256>>>(x, cats, myp);

    dim3 gBig128(8, (MROWS + 127)/128);   // N=1024, K=256 GEMMs

    // ---- layer 1 (d=1): K=49 input GEMM, then 10 clusters x 1 chain ----
    sgemm_nt<0,0><<<dim3(16, (MROWS+63)/64), 256>>>(
        pWin, nullptr, Wih1, b1, pZ, MROWS, 1024, FIN);
    lstm_chain<1,1><<<80, 256>>>(pZ, Whh1, pHA);

    // ---- layer 2 (d=2): -> hB (kept for residual) ----
    sgemm128<0><<<gBig128, 256>>>(pHA, Wih2, b2, pZ, MROWS, 1024, HN);
    lstm_chain<2,2><<<80, 256>>>(pZ, Whh2, pHB);

    // ---- layer 3 (d=2) ----
    sgemm128<0><<<gBig128, 256>>>(pHB, Wih3, b3, pZ, MROWS, 1024, HN);
    lstm_chain<2,2><<<80, 256>>>(pZ, Whh3, pHA);

    // ---- layer 4 (d=6): 15 clusters x 4 chains ----
    sgemm128<0><<<gBig128, 256>>>(pHA, Wih4, b4, pZ, MROWS, 1024, HN);
    lstm_chain<4,6><<<120, 256>>>(pZ, Whh4, pHA);

    // ---- linear + tanh with fused residual (hA + hB) -> g_Z (64x64 tiles) --
    sgemm_nt<1,1><<<dim3(4, (MROWS+63)/64), 256>>>(
        pHA, pHB, lW, lb, pZ, MROWS, HN, HN);

    // ---- score ----
    sgemm_nt<0,0><<<dim3(1, (MROWS+63)/64), 256>>>(
        pZ, nullptr, sW, sb, pRnn, MROWS, OUTN, HN);

    // ---- assemble outputs ----
    outputs_kernel<<<1024, 256>>>(x, val, (float*)d_out, out_size);
}